// round 17
// baseline (speedup 1.0000x reference)
#include <cuda_runtime.h>

#define HH 256
#define WW 256
#define NI 16
#define CC 3
#define HW (HH * WW)
#define NHALF 8

__device__ float d_mscratch[8 * HW];   // mask partial for z=1, up to B=8

__device__ __forceinline__ void stcs(float* p, float v) {
#if __CUDA_ARCH__ >= 800
    __stcs(p, v);
#else
    *p = v;
#endif
}

__device__ __forceinline__ void stcs4(float* p, float4 v) {
#if __CUDA_ARCH__ >= 800
    __stcs((float4*)p, v);
#else
    *(float4*)p = v;
#endif
}

// grid: (B*H, 2) ; block = 256 threads (one full row, half the instances)
__global__ __launch_bounds__(256, 7)
void warp_renderer_kernel(
    const float* __restrict__ g0,           // [B,NI,C,H,W]
    const float* __restrict__ m0,           // [B,NI,1,H,W]
    const float* __restrict__ mode_logits,  // [B,NI,5]
    const float* __restrict__ tp,           // [B,NI,6]
    const float* __restrict__ alpha,        // [B,NI,1]
    const float* __restrict__ inst_valid,   // [B,NI]
    float* __restrict__ out,
    int B)
{
    __shared__ int   s_nact, s_ninact;
    __shared__ int   s_act_ni[NHALF];
    __shared__ float s_act_coef[NHALF];
    __shared__ float s_act_t0[NHALF], s_act_t3[NHALF];
    __shared__ float s_act_bx[NHALF], s_act_by[NHALF];
    __shared__ int   s_inact_ni[NHALF];

    const int b = blockIdx.x >> 8;        // blockIdx.x = b*H + y
    const int y = blockIdx.x & 255;
    const int z = blockIdx.y;             // instance half: 0 -> 0..7, 1 -> 8..15
    const int x = threadIdx.x;

    // --- per-instance precompute + active compaction (lanes 0..7 of warp 0) ---
    if (threadIdx.x < NHALF) {
        const int lane = threadIdx.x;
        const int ni   = z * NHALF + lane;
        const int inst = b * NI + ni;
        const float* L = mode_logits + inst * 5;
        int mode = 0;
        float best = L[0];
        #pragma unroll
        for (int k = 1; k < 5; ++k) {
            float v = L[k];
            if (v > best) { best = v; mode = k; }  // first-max argmax
        }
        float coef;
        if (mode == 0 || mode == 2 || mode == 4) coef = 1.0f;       // static-like
        else if (mode == 3)                      coef = alpha[inst]; // blink
        else                                     coef = 0.0f;        // mode 1
        coef *= inst_valid[inst];

        const bool active = (coef != 0.0f);
        const unsigned mask = __ballot_sync(0x000000FFu, active);
        const unsigned lower = (1u << lane) - 1u;

        if (active) {
            const int pos = __popc(mask & lower);
            const float t0 = tp[inst * 6 + 0];
            const float t1 = tp[inst * 6 + 1];
            const float t2 = tp[inst * 6 + 2];
            const float t3 = tp[inst * 6 + 3];
            const float t4 = tp[inst * 6 + 4];
            const float t5 = tp[inst * 6 + 5];
            const float ys = (2.0f * (float)y + 1.0f) * (1.0f / (float)HH) - 1.0f;
            // ix = t0*x + bx ; iy = t3*x + by   (full chain folded)
            const float bx = 128.0f * (t1 * ys + t2) + 127.5f + 0.5f * t0 - 128.0f * t0;
            const float by = 128.0f * (t4 * ys + t5) + 127.5f + 0.5f * t3 - 128.0f * t3;
            s_act_ni[pos]   = ni;
            s_act_coef[pos] = coef;
            s_act_t0[pos]   = t0;
            s_act_t3[pos]   = t3;
            s_act_bx[pos]   = bx;
            s_act_by[pos]   = by;
        } else {
            const int pos = __popc((~mask) & 0xFFu & lower);
            s_inact_ni[pos] = ni;
        }
        if (lane == 0) {
            s_nact   = __popc(mask);
            s_ninact = NHALF - __popc(mask);
        }
    }
    __syncthreads();

    const int pix = y * WW + x;
    const float xf = (float)x;

    const int n_gpi = B * NI * CC * HW;
    const int n_mpi = B * NI * HW;
    float* __restrict__ out_gpi  = out;
    float* __restrict__ out_mpi  = out + n_gpi;
    float* __restrict__ out_gmid = out + n_gpi + n_mpi;
    float* __restrict__ out_mmid = out_gmid + B * CC * HW;
    float* __restrict__ out_ibas = out_mmid + B * HW;   // z=1 uses as gsum scratch

    // --- zero stores for inactive instances: float4 remap ---
    {
        const int arr  = threadIdx.x >> 6;            // 0..3
        const int seg  = (threadIdx.x & 63) * 4;      // 0,4,...,252
        const int zoff = y * WW + seg;
        const float4 z4 = make_float4(0.f, 0.f, 0.f, 0.f);
        const int ninact = s_ninact;
        for (int k = 0; k < ninact; ++k) {
            const int ni = s_inact_ni[k];
            float* dst = (arr < 3)
                ? (out_gpi + (b * NI + ni) * CC * HW + arr * HW + zoff)
                : (out_mpi + (b * NI + ni) * HW + zoff);
            stcs4(dst, z4);
        }
    }

    float gacc0 = 0.0f, gacc1 = 0.0f, gacc2 = 0.0f, macc = 0.0f;

    // --- hot loop: active instances of this half ---
    const int nact = s_nact;
    for (int j = 0; j < nact; ++j) {
        const int   ni   = s_act_ni[j];
        const float coef = s_act_coef[j];
        const int base_g = (b * NI + ni) * CC * HW;
        const int base_m = (b * NI + ni) * HW;

        const float ix = fmaf(s_act_t0[j], xf, s_act_bx[j]);
        const float iy = fmaf(s_act_t3[j], xf, s_act_by[j]);

        const int x0 = __float2int_rd(ix);
        const int y0 = __float2int_rd(iy);
        const float wx1 = ix - (float)x0;
        const float wy1 = iy - (float)y0;
        const float wx0 = 1.0f - wx1;
        const float wy0 = 1.0f - wy1;
        const int x1 = x0 + 1, y1 = y0 + 1;

        const bool vx0 = (x0 >= 0) & (x0 < WW);
        const bool vx1 = (x1 >= 0) & (x1 < WW);
        const bool vy0 = (y0 >= 0) & (y0 < HH);
        const bool vy1 = (y1 >= 0) & (y1 < HH);

        const int x0c = min(max(x0, 0), WW - 1);
        const int x1c = min(max(x1, 0), WW - 1);
        const int y0c = min(max(y0, 0), HH - 1);
        const int y1c = min(max(y1, 0), HH - 1);

        const float wy0c = wy0 * coef;
        const float wy1c = wy1 * coef;
        const float w00 = wx0 * wy0c * ((vx0 & vy0) ? 1.0f : 0.0f);
        const float w10 = wx1 * wy0c * ((vx1 & vy0) ? 1.0f : 0.0f);
        const float w01 = wx0 * wy1c * ((vx0 & vy1) ? 1.0f : 0.0f);
        const float w11 = wx1 * wy1c * ((vx1 & vy1) ? 1.0f : 0.0f);

        const int i00 = y0c * WW + x0c;
        const int i10 = y0c * WW + x1c;
        const int i01 = y1c * WW + x0c;
        const int i11 = y1c * WW + x1c;

        const float* __restrict__ s0 = g0 + base_g;
        const float* __restrict__ s1 = s0 + HW;
        const float* __restrict__ s2 = s1 + HW;
        const float* __restrict__ sm = m0 + base_m;

        const float a00 = __ldg(s0 + i00), a10 = __ldg(s0 + i10),
                    a01 = __ldg(s0 + i01), a11 = __ldg(s0 + i11);
        const float b00 = __ldg(s1 + i00), b10 = __ldg(s1 + i10),
                    b01 = __ldg(s1 + i01), b11 = __ldg(s1 + i11);
        const float c00 = __ldg(s2 + i00), c10 = __ldg(s2 + i10),
                    c01 = __ldg(s2 + i01), c11 = __ldg(s2 + i11);
        const float d00 = __ldg(sm + i00), d10 = __ldg(sm + i10),
                    d01 = __ldg(sm + i01), d11 = __ldg(sm + i11);

        const float g0v = w00 * a00 + w10 * a10 + w01 * a01 + w11 * a11;
        const float g1v = w00 * b00 + w10 * b10 + w01 * b01 + w11 * b11;
        const float g2v = w00 * c00 + w10 * c10 + w01 * c01 + w11 * c11;
        const float mv  = w00 * d00 + w10 * d10 + w01 * d01 + w11 * d11;

        stcs(out_gpi + base_g + pix,          g0v);
        stcs(out_gpi + base_g + HW + pix,     g1v);
        stcs(out_gpi + base_g + 2 * HW + pix, g2v);
        stcs(out_mpi + base_m + pix,          mv);

        gacc0 += g0v; gacc1 += g1v; gacc2 += g2v; macc += mv;
    }

    // --- write partial sums ---
    const int bg = b * CC * HW + pix;
    if (z == 0) {
        stcs(out_gmid + bg,          gacc0);
        stcs(out_gmid + bg + HW,     gacc1);
        stcs(out_gmid + bg + 2 * HW, gacc2);
        stcs(out_mmid + b * HW + pix, macc);            // unclipped partial
    } else {
        stcs(out_ibas + bg,          gacc0);            // scratch (overwritten by combine)
        stcs(out_ibas + bg + HW,     gacc1);
        stcs(out_ibas + bg + 2 * HW, gacc2);
        stcs(d_mscratch + b * HW + pix, macc);
    }
}

// ───────────── combine: gmid = p0+p1, mmid = clip, ibas = i_bg + gmid ─────────────
__global__ __launch_bounds__(256)
void combine_kernel(
    const float* __restrict__ i_bg,      // [B,C,H,W]
    float* __restrict__ out,
    int B)
{
    const int b = blockIdx.x >> 8;
    const int y = blockIdx.x & 255;
    const int pix = y * WW + threadIdx.x;

    const int n_gpi = B * NI * CC * HW;
    const int n_mpi = B * NI * HW;
    float* __restrict__ out_gmid = out + n_gpi + n_mpi;
    float* __restrict__ out_mmid = out_gmid + B * CC * HW;
    float* __restrict__ out_ibas = out_mmid + B * HW;

    const int bg = b * CC * HW + pix;

    const float p00 = out_gmid[bg];
    const float p01 = out_gmid[bg + HW];
    const float p02 = out_gmid[bg + 2 * HW];
    const float p10 = out_ibas[bg];
    const float p11 = out_ibas[bg + HW];
    const float p12 = out_ibas[bg + 2 * HW];
    const float m0p = out_mmid[b * HW + pix];
    const float m1p = d_mscratch[b * HW + pix];

    const float gm0 = p00 + p10;
    const float gm1 = p01 + p11;
    const float gm2 = p02 + p12;

    stcs(out_gmid + bg,          gm0);
    stcs(out_gmid + bg + HW,     gm1);
    stcs(out_gmid + bg + 2 * HW, gm2);
    stcs(out_mmid + b * HW + pix, fminf(fmaxf(m0p + m1p, 0.0f), 1.0f));
    stcs(out_ibas + bg,          __ldg(i_bg + bg)          + gm0);
    stcs(out_ibas + bg + HW,     __ldg(i_bg + bg + HW)     + gm1);
    stcs(out_ibas + bg + 2 * HW, __ldg(i_bg + bg + 2 * HW) + gm2);
}

extern "C" void kernel_launch(void* const* d_in, const int* in_sizes, int n_in,
                              void* d_out, int out_size) {
    const float* g0          = (const float*)d_in[0];
    const float* m0          = (const float*)d_in[1];
    const float* mode_logits = (const float*)d_in[2];
    const float* tp          = (const float*)d_in[3];
    const float* alpha       = (const float*)d_in[4];
    const float* inst_valid  = (const float*)d_in[5];
    const float* i_bg        = (const float*)d_in[6];
    float* out = (float*)d_out;

    const int B = in_sizes[0] / (NI * CC * HW);

    dim3 grid1(B * HH, 2);
    warp_renderer_kernel<<<grid1, 256>>>(g0, m0, mode_logits, tp, alpha,
                                         inst_valid, out, B);

    dim3 grid2(B * HH);
    combine_kernel<<<grid2, 256>>>(i_bg, out, B);
}